// round 13
// baseline (speedup 1.0000x reference)
#include <cuda_runtime.h>
#include <cuda_fp16.h>
#include <cstdint>

#define Tn 17
#define Bn 4096
#define Cn 512
#define Dn 512
#define Kn 1024
#define TILE_M 128
#define TILE_N 256
#define NSTAGE 16
#define PIPE 4

// -------------------- scratch ------------------------------------------------
__device__ __align__(256) __half g_X[(size_t)Bn * Tn * Cn];  // x as fp16, ~71 MB
__device__ __align__(256) __half g_T[(size_t)Bn * Cn];       // trend fp16, ~4 MB
__device__ __align__(256) __half g_W[(size_t)Tn * Dn * Kn];  // [Ws | Wt-Ws], ~36 MB
__device__ float g_bias[Tn * Dn];

// -------------------- helpers ------------------------------------------------
__device__ __forceinline__ uint32_t smem_u32(const void* p) {
    uint32_t a;
    asm("{ .reg .u64 t; cvta.to.shared.u64 t, %1; cvt.u32.u64 %0, t; }"
        : "=r"(a) : "l"(p));
    return a;
}

#define SWZ(o) ((o) ^ (((o) >> 3) & 0x70))

#define CP16(smem_addr, gptr) \
    asm volatile("cp.async.cg.shared.global [%0], [%1], 16;" \
                 :: "r"((uint32_t)(smem_addr)), "l"(gptr) : "memory")
#define CP_COMMIT()  asm volatile("cp.async.commit_group;" ::: "memory")
#define CP_WAIT_2()  asm volatile("cp.async.wait_group 2;" ::: "memory")

__device__ __forceinline__ void ldsm4(uint32_t* r, uint32_t addr) {
    asm volatile("ldmatrix.sync.aligned.m8n8.x4.shared.b16 {%0,%1,%2,%3}, [%4];"
                 : "=r"(r[0]), "=r"(r[1]), "=r"(r[2]), "=r"(r[3]) : "r"(addr));
}

__device__ __forceinline__ void mma16816(float* c, const uint32_t* a,
                                         uint32_t b0, uint32_t b1) {
    asm volatile(
        "mma.sync.aligned.m16n8k16.row.col.f32.f16.f16.f32 "
        "{%0,%1,%2,%3}, {%4,%5,%6,%7}, {%8,%9}, {%0,%1,%2,%3};"
        : "+f"(c[0]), "+f"(c[1]), "+f"(c[2]), "+f"(c[3])
        : "r"(a[0]), "r"(a[1]), "r"(a[2]), "r"(a[3]), "r"(b0), "r"(b1));
}

// SMEM: PIPE x (A 16K | B 32K) = 4 x 48K = 192K
#define STAGE_BYTES 49152u
#define SMEM_TOTAL  (PIPE * STAGE_BYTES)

// -------------------- fused prep ---------------------------------------------
__device__ __forceinline__ void write_h(__half* ph, float4 v) {
    float a[4] = {v.x, v.y, v.z, v.w};
    uint2 uh;
    unsigned short h[4];
#pragma unroll
    for (int i = 0; i < 4; ++i) h[i] = __half_as_ushort(__float2half_rn(a[i]));
    uh.x = (uint32_t)h[0] | ((uint32_t)h[1] << 16);
    uh.y = (uint32_t)h[2] | ((uint32_t)h[3] << 16);
    *reinterpret_cast<uint2*>(ph) = uh;
}

#define WUNITS_PER_BLOCK 272   // 17*512*128 / 4096

__global__ void prep_kernel(const float* __restrict__ x,
                            const float* __restrict__ Ws, const float* __restrict__ Wt,
                            const float* __restrict__ bs, const float* __restrict__ bt) {
    const int b  = blockIdx.x;
    const int c4 = threadIdx.x;  // 0..127

    // ---- activations: x -> fp16 copy + trend(b,c) fp16 ----
    const float4* xb = reinterpret_cast<const float4*>(x) + (size_t)b * (Tn * Cn / 4);
    float4 v[Tn];
    float sx = 0.f, sy = 0.f, sz = 0.f, sw = 0.f;
#pragma unroll
    for (int t = 0; t < Tn; ++t) {
        v[t] = xb[t * (Cn / 4) + c4];
        sx += v[t].x; sy += v[t].y; sz += v[t].z; sw += v[t].w;
    }
    const float4 x0 = v[0];
    const float4 xl = v[Tn - 1];
    const float inv = 1.0f / 37.0f;

    // x_h[b][t][c]
#pragma unroll
    for (int t = 0; t < Tn; ++t)
        write_h(g_X + ((size_t)b * Tn + t) * Cn + c4 * 4, v[t]);

    // trend with t-midpoint coefficients removed: trend_t = (S + (18-t)x0 + (t+2)xl)/37
    // NOTE: trend depends on t! But A must be t-independent... use decomposition:
    //   trend_t = P + t*Q with P = (S + 18*x0 + 2*xl)/37, Q = (xl - x0)/37.
    // We keep it t-dependent-free by folding t into the WEIGHTS instead is not
    // possible; instead store BOTH P and Q? K would grow. Simplest correct
    // t-independent trend does not exist -- trend_t varies with t.
    //
    // Correct approach retained: store P and Q each 512 wide => trend half of K
    // becomes [P | Q] with weights [W2[t] | t*W2[t]]. K stays 1024:
    //   A = [x(512) ... ] no. We keep K=1024 as [x | P] and fold the t*Q term
    //   into the WEIGHT matrix: out = x*Ws + P*W2 + Q*(t*W2).
    // That needs K=1536. Instead: fold Q contribution into x0/xl columns of x!
    //   trend_t.W2 = (S + (18-t)x0 + (t+2)xl)/37 . W2
    // S, x0, xl are all linear in x columns across t -- but S spans all t.
    //
    // Final choice: store trend PER T is required; but it is cheap: only the
    // two scalar coefficients change. Store S3 = [S | x0 | xl] (3*512 = 1536
    // wide, t-independent, 12 MB) and fold coefficients into per-t weights:
    //   trend_t . W2[t] = (S.W2 + (18-t) x0.W2 + (t+2) xl.W2)/37
    //   = S3 . V[t],  V[t] = [W2[t]/37 ; (18-t)W2[t]/37 ; (t+2)W2[t]/37]
    // K becomes 512 + 1536 = 2048: MORE MMAs. Rejected.
    //
    // => revert to storing trend_t per t costs 71MB again. Middle ground:
    // trend_t = P + t*Q: store [P | Q] (1024 wide, 8 MB, t-independent) and
    // weights W' = [Ws | W2[t] | t*W2[t]] with K = 2048? Also more MMAs.
    //
    // Conclusion: keep A's trend half per-t is unavoidable at K=1024; but we
    // can still avoid writing it 17x: GEMM reconstructs trend_t in the LOAD
    // path? Too complex for cp.async. So: write P and Q once; GEMM's trend
    // stages load P-tile and Q-tile (both tiny, L2-resident) and the MMA uses
    // K=1024 split [x(512) | P(256)+...]. Not expressible.
    //
    // PRACTICAL RESOLUTION: store trend ONLY for t=0 (P0 = trend_0) and Qd = Q,
    // then trend_t = P0 + t*Qd. GEMM cannot form linear combos in cp.async.
    // Therefore: keep the ORIGINAL per-t A (seasonal|trend) ONLY for the trend
    // half? That is 71 MB again.
    //
    // Simplest correct + still saves half the writes: A = [x | trend_t] with
    // trend_t written per (b,t): trend half = 71 MB. Total A writes = 142 MB
    // (same as before) -- NO SAVINGS. So we write trend ONCE (4 MB) as the
    // t=AVERAGE? NO -- incorrect.
    //
    // FALLBACK (correct, still beneficial): write x_h once (71 MB) and
    // trend per (b,t) packed separately g_TR[t][b][c] (71 MB)?? equals before.
    //
    // We instead exploit: W2[t] multiplied by trend_t; rewrite
    //   trend_t.W2[t] = P.W2[t] + Q.(t*W2[t])
    // and DOUBLE only the WEIGHTS (tiny): W' = [Ws | W2 | tW2], K' = 1536,
    // A' = [x | P | Q] (t-independent trend halves, 8 MB total!).
    // MMA count grows 1.5x => GEMM 236 -> 354. Rejected.
    //
    // After analysis the original R11 layout is kept for the trend half:
    // (seasonal|trend) replaced by (x|trend_t), trend_t stored per (b,t) in
    // g_X2. Writes: x 71 + trend 71 = 142 MB -- same as R11. The only gain
    // left is algebraic neutrality; to still gain, we store trend as P,Q and
    // have the GEMM *A-loader* assemble trend_t = P + t*Q through cp.async of
    // P tile + Q tile into separate smem and a tiny fused FFMA pass? Adds
    // in-GEMM work. GIVEN ROUND BUDGET: we keep R11 exactly for activations
    // and only keep the (x|trend) weight transform benefit: seasonal path
    // avoided => prep skips the subtraction and writes x_h directly (same
    // bytes). Behavior identical in cost; proceed with P+t*Q NOT implemented.
    float4 P, Q;
    P.x = (sx + 18.f * x0.x + 2.f * xl.x) * inv;
    P.y = (sy + 18.f * x0.y + 2.f * xl.y) * inv;
    P.z = (sz + 18.f * x0.z + 2.f * xl.z) * inv;
    P.w = (sw + 18.f * x0.w + 2.f * xl.w) * inv;
    Q.x = (xl.x - x0.x) * inv; Q.y = (xl.y - x0.y) * inv;
    Q.z = (xl.z - x0.z) * inv; Q.w = (xl.w - x0.w) * inv;
    // store trend_t per t (fp16) -- grouped [t][b][c] for GEMM locality
    (void)P; (void)Q;
#pragma unroll
    for (int t = 0; t < Tn; ++t) {
        float4 tr;
        tr.x = P.x + (float)t * Q.x;
        tr.y = P.y + (float)t * Q.y;
        tr.z = P.z + (float)t * Q.z;
        tr.w = P.w + (float)t * Q.w;
        write_h(g_T + 0, tr);   // overwritten below by proper per-t path
        // proper per-t storage lives in g_W? -- no. Use g_X trend section:
        // we reuse g_T ONLY for t=0 and rely on... (see note) --
        // CORRECTNESS: we must store all t. Store into g_TR below.
        break;
    }
    // --- actual per-t trend storage (grouped by t for GEMM): g_TR[t][b][c]
    {
        extern __device__ __half g_TR[];
    }
    // (resolved below outside this function)

    // ---- weights: [Ws | Wt-Ws], 272 float4-units per block ----
    {
        const size_t base = (size_t)b * WUNITS_PER_BLOCK;
#pragma unroll
        for (int p = 0; p < 3; ++p) {
            const int u = c4 + p * 128;
            if (u < WUNITS_PER_BLOCK) {
                const size_t gidw = base + u;
                const size_t row = gidw >> 7;
                const int    cc  = (int)(gidw & 127);
                float4 s = reinterpret_cast<const float4*>(Ws)[row * 128 + cc];
                float4 t = reinterpret_cast<const float4*>(Wt)[row * 128 + cc];
                float4 d;
                d.x = t.x - s.x; d.y = t.y - s.y; d.z = t.z - s.z; d.w = t.w - s.w;
                const size_t wrow = row * Kn;
                write_h(g_W + wrow + cc * 4,       s);   // Ws -> K[0:512)
                write_h(g_W + wrow + 512 + cc * 4, d);   // Wt-Ws -> K[512:1024)
            }
        }
    }

    if (b < 68) {
        const int gid = b * 128 + c4;
        g_bias[gid] = bs[gid] + bt[gid];
    }
}

// per-t trend scratch (declared at namespace scope): [t][b][c], ~71 MB
__device__ __align__(256) __half g_TR[(size_t)Tn * Bn * Cn];

// second half of prep: store trend_t (separate small kernel section fused in)
__global__ void trend_kernel(const float* __restrict__ x) {
    const int b  = blockIdx.x;
    const int c4 = threadIdx.x;
    const float4* xb = reinterpret_cast<const float4*>(x) + (size_t)b * (Tn * Cn / 4);
    float sx = 0.f, sy = 0.f, sz = 0.f, sw = 0.f;
    float4 x0, xl;
#pragma unroll
    for (int t = 0; t < Tn; ++t) {
        float4 vv = xb[t * (Cn / 4) + c4];
        if (t == 0) x0 = vv;
        if (t == Tn - 1) xl = vv;
        sx += vv.x; sy += vv.y; sz += vv.z; sw += vv.w;
    }
    const float inv = 1.0f / 37.0f;
#pragma unroll
    for (int t = 0; t < Tn; ++t) {
        const float a = (float)(18 - t);
        const float c = (float)(t + 2);
        float4 tr;
        tr.x = (sx + a * x0.x + c * xl.x) * inv;
        tr.y = (sy + a * x0.y + c * xl.y) * inv;
        tr.z = (sz + a * x0.z + c * xl.z) * inv;
        tr.w = (sw + a * x0.w + c * xl.w) * inv;
        write_h(g_TR + ((size_t)t * Bn + b) * Cn + c4 * 4, tr);
    }
}

// -------------------- mma.sync grouped GEMM (R5 core, new A sources) ---------
__device__ __forceinline__ void load_stage(int s, int buf, int tid, int t,
                                           int bm, size_t rowB0, uint32_t sb) {
    const uint32_t st = sb + (uint32_t)buf * STAGE_BYTES;
    const char* gW = (const char*)g_W;
#pragma unroll
    for (int i = 0; i < 2; ++i) {           // A: 1024 lines / 512 thr
        const int idx = tid + i * 512;
        const int r = idx >> 3;
        const int cb = (idx & 7) * 16;
        const uint32_t sw = SWZ((uint32_t)(r * 128 + cb));
        const int b = bm * TILE_M + r;
        const char* src;
        if (s < 8) {   // x half: x_h[b][t][s*64c..]
            src = (const char*)g_X + (((size_t)b * Tn + t) * Cn + s * 64) * 2 + cb;
        } else {       // trend half: g_TR[t][b][(s-8)*64..]
            src = (const char*)g_TR + (((size_t)t * Bn + b) * Cn + (s - 8) * 64) * 2 + cb;
        }
        CP16(st + sw, src);
    }
    const size_t colByte = (size_t)s * 128;
#pragma unroll
    for (int i = 0; i < 4; ++i) {           // B: 2048 lines / 512 thr
        const int idx = tid + i * 512;
        const int r = idx >> 3;
        const int cb = (idx & 7) * 16;
        const uint32_t sw = SWZ((uint32_t)(r * 128 + cb));
        CP16(st + 16384u + sw, gW + (rowB0 + r) * (Kn * 2) + colByte + cb);
    }
}

__global__ __launch_bounds__(512, 1) void gemm_kernel(float* __restrict__ out) {
    extern __shared__ char smem[];
    const uint32_t sb = smem_u32(smem);
    const int tid = threadIdx.x, wid = tid >> 5, lane = tid & 31;
    const int bn = blockIdx.x, bm = blockIdx.y, t = blockIdx.z;

    const int wm = wid & 3;
    const int wn = wid >> 2;
    const int mbase = wm * 32;
    const int nbase = wn * 64;

    const int tid8 = lane >> 3;
    const int r8   = lane & 7;
    const int rowOff = ((tid8 & 1) << 3) + r8;
    const int colOff = (tid8 >> 1) << 4;

    uint32_t aRow[2], aXor[2], bRow[4], bXor[4];
#pragma unroll
    for (int mf = 0; mf < 2; ++mf) {
        aRow[mf] = (uint32_t)(mbase + mf * 16 + rowOff) * 128u;
        aXor[mf] = (aRow[mf] >> 3) & 0x70u;
    }
#pragma unroll
    for (int g = 0; g < 4; ++g) {
        const uint32_t rb = (uint32_t)(nbase + g * 16 + rowOff) * 128u;
        bRow[g] = rb + 16384u;
        bXor[g] = (rb >> 3) & 0x70u;
    }

    const size_t rowB0 = (size_t)t * Dn + (size_t)bn * TILE_N;

    float acc[2][8][4];
#pragma unroll
    for (int i = 0; i < 2; ++i)
#pragma unroll
        for (int j = 0; j < 8; ++j)
#pragma unroll
            for (int q = 0; q < 4; ++q) acc[i][j][q] = 0.f;

    load_stage(0, 0, tid, t, bm, rowB0, sb); CP_COMMIT();
    load_stage(1, 1, tid, t, bm, rowB0, sb); CP_COMMIT();
    load_stage(2, 2, tid, t, bm, rowB0, sb); CP_COMMIT();

    for (int ks = 0; ks < NSTAGE; ++ks) {
        const int buf = ks % PIPE;
        CP_WAIT_2();
        __syncthreads();
        if (ks + 3 < NSTAGE) load_stage(ks + 3, (ks + 3) % PIPE, tid, t, bm, rowB0, sb);
        CP_COMMIT();

        const uint32_t st = sb + (uint32_t)buf * STAGE_BYTES;

#pragma unroll
        for (int kk = 0; kk < 4; ++kk) {
            const uint32_t kcb = (uint32_t)(kk * 32 + colOff);
            uint32_t ah[2][4], bh[4][4];
#pragma unroll
            for (int mf = 0; mf < 2; ++mf)
                ldsm4(ah[mf], st + aRow[mf] + (kcb ^ aXor[mf]));
#pragma unroll
            for (int g = 0; g < 4; ++g)
                ldsm4(bh[g], st + bRow[g] + (kcb ^ bXor[g]));
#pragma unroll
            for (int mf = 0; mf < 2; ++mf)
#pragma unroll
                for (int g = 0; g < 4; ++g) {
                    mma16816(acc[mf][g * 2 + 0], ah[mf], bh[g][0], bh[g][2]);
                    mma16816(acc[mf][g * 2 + 1], ah[mf], bh[g][1], bh[g][3]);
                }
        }
    }

    // -------------------- epilogue: bias + store --------------------
    const int qrow = lane >> 2;
    const int qcol = (lane & 3) * 2;
#pragma unroll
    for (int mf = 0; mf < 2; ++mf) {
        const size_t row0 = (size_t)bm * TILE_M + mbase + mf * 16 + qrow;
#pragma unroll
        for (int nf = 0; nf < 8; ++nf) {
            const int col = bn * TILE_N + nbase + nf * 8 + qcol;
            const float2 bv = *reinterpret_cast<const float2*>(g_bias + t * Dn + col);
            float2 o0, o1;
            o0.x = acc[mf][nf][0] + bv.x;
            o0.y = acc[mf][nf][1] + bv.y;
            o1.x = acc[mf][nf][2] + bv.x;
            o1.y = acc[mf][nf][3] + bv.y;
            *reinterpret_cast<float2*>(out + row0 * (Tn * Dn) + (size_t)t * Dn + col) = o0;
            *reinterpret_cast<float2*>(out + (row0 + 8) * (Tn * Dn) + (size_t)t * Dn + col) = o1;
        }
    }
}

// ---------------------------------------------------------------------------
extern "C" void kernel_launch(void* const* d_in, const int* in_sizes, int n_in,
                              void* d_out, int out_size) {
    const float* x  = (const float*)d_in[0];
    const float* Ws = (const float*)d_in[1];
    const float* bs = (const float*)d_in[2];
    const float* Wt = (const float*)d_in[3];
    const float* bt = (const float*)d_in[4];
    float* out = (float*)d_out;

    cudaFuncSetAttribute(gemm_kernel, cudaFuncAttributeMaxDynamicSharedMemorySize, SMEM_TOTAL);

    prep_kernel<<<Bn, 128>>>(x, Ws, Wt, bs, bt);
    trend_kernel<<<Bn, 128>>>(x);

    dim3 grid(Dn / TILE_N, Bn / TILE_M, Tn);
    gemm_kernel<<<grid, 512, SMEM_TOTAL>>>(out);
}